// round 8
// baseline (speedup 1.0000x reference)
#include <cuda_runtime.h>
#include <cuda_bf16.h>

// DETR post-processor, 2-launch pipeline:
//   scan_batched : 1 CTA per batch-segment (8 x 2500 float4 per batch), FMNMX
//                  screen at t=2.4 -> SMEM buffer; then 2 warps bitonic-sort
//                  the <=128 candidates in registers (direction = seg parity:
//                  even desc / odd asc) and write the sorted chunk to a FIXED
//                  128-slot region of g_cand (zero padded). Streaming is at
//                  the LTS ceiling; the sort tail hides behind other CTAs.
//                  Segment overflow (>128, 5.1 sigma) poisons g_cnt.
//   rank_kernel  : per batch, the 8 alternating sorted chunks are already
//                  bitonic at stage k=256 -> run ONLY merge stages k=256,512,
//                  1024 (18 shfl + 9 smem phases vs 55 total), decode top-300
//                  from registers. Exact histogram fallback (full sort) if
//                  count outside [300,1024] or chunks not presorted.

#define NCLS    80
#define NQ      1000
#define NPB     80000
#define NF4B    20000          // float4 per batch
#define NB      256
#define TOPK    300
#define CAP     1024
#define THR     2.4f
#define SEGS    8              // CTAs per batch
#define SEGF4   2500           // float4 per CTA
#define SEGCAP  128            // slots per segment chunk (lambda=82, sigma=9)
#define SCTA    512
#define BUFCAP  384            // smem collection buffer
#define GPAD    32             // g_cnt stride (128B) -> spread LTS slices
#define BTHREADS 512
#define NHIST   4096

__device__ unsigned long long g_cand[NB][CAP];
__device__ int g_cnt[NB * GPAD];

__device__ __forceinline__ unsigned fkey(float f) {
    unsigned u = __float_as_uint(f);
    return (u & 0x80000000u) ? ~u : (u | 0x80000000u);  // monotonic float->uint
}
__device__ __forceinline__ float key2f(unsigned k) {
    return (k & 0x80000000u) ? __uint_as_float(k & 0x7fffffffu)
                             : __uint_as_float(~k);
}
__device__ __forceinline__ unsigned long long pack(float val, unsigned loc) {
    return ((unsigned long long)fkey(val) << 32) | (unsigned)(0xFFFFFFFFu - loc);
}

// ---- bitonic helpers (element index i, phase j, block k; inv flips dir) ----
__device__ __forceinline__ unsigned long long upick(
    unsigned long long v, unsigned long long o, int i, int j, int k, bool inv)
{
    const bool keep_max = ((((i & j) == 0) == ((i & k) == 0))) ^ inv;
    const unsigned long long mx = v > o ? v : o;
    const unsigned long long mn = v > o ? o : v;
    return keep_max ? mx : mn;
}
__device__ __forceinline__ unsigned long long ushfl(
    unsigned long long v, int i, int j, int k, bool inv)
{
    const unsigned long long o = __shfl_xor_sync(0xFFFFFFFFu, v, j);
    return upick(v, o, i, j, k, inv);
}
__device__ __forceinline__ void ulocal32(
    unsigned long long& r0, unsigned long long& r1, int i0, int k, bool inv)
{
    const bool desc = ((i0 & k) == 0) != inv;
    const unsigned long long hi = r0 > r1 ? r0 : r1;
    const unsigned long long lo = r0 > r1 ? r1 : r0;
    r0 = desc ? hi : lo;
    r1 = desc ? lo : hi;
}

// ---- batch-aligned scan: CTA c covers batch c/8, segment c%8 ----
__global__ __launch_bounds__(SCTA, 3)
void scan_batched(const float4* __restrict__ lg)
{
    __shared__ unsigned long long s_buf[BUFCAP];
    __shared__ int s_cnt;

    const unsigned c   = blockIdx.x;
    const unsigned n   = c >> 3;
    const unsigned seg = c & 7u;
    const unsigned t   = threadIdx.x;
    const unsigned f4base = n * (unsigned)NF4B + seg * (unsigned)SEGF4;

    if (t == 0) s_cnt = 0;
    __syncthreads();

    // 2500 = 4*512 + 452 : 4 full strides + partial 5th
    float4 v[5];
    #pragma unroll
    for (int k = 0; k < 4; k++) v[k] = lg[f4base + t + k * SCTA];
    const bool has5 = (t < (unsigned)(SEGF4 - 4 * SCTA));   // t < 452
    if (has5) v[4] = lg[f4base + t + 4 * SCTA];

    #pragma unroll
    for (int k = 0; k < 5; k++) {
        if (k == 4 && !has5) continue;
        const float4 x = v[k];
        if (fmaxf(fmaxf(x.x, x.y), fmaxf(x.z, x.w)) > THR) {  // ~3.2% taken
            const unsigned loc0 = (seg * (unsigned)SEGF4 + t + (unsigned)k * SCTA) * 4u;
            if (x.x > THR) { int p = atomicAdd(&s_cnt, 1); if (p < BUFCAP) s_buf[p] = pack(x.x, loc0 + 0u); }
            if (x.y > THR) { int p = atomicAdd(&s_cnt, 1); if (p < BUFCAP) s_buf[p] = pack(x.y, loc0 + 1u); }
            if (x.z > THR) { int p = atomicAdd(&s_cnt, 1); if (p < BUFCAP) s_buf[p] = pack(x.z, loc0 + 2u); }
            if (x.w > THR) { int p = atomicAdd(&s_cnt, 1); if (p < BUFCAP) s_buf[p] = pack(x.w, loc0 + 3u); }
        }
    }
    __syncthreads();

    const int cnt = s_cnt;
    if (t == 0)
        atomicAdd(&g_cnt[n * GPAD], (cnt > SEGCAP) ? 1000000 : cnt);

    if (cnt <= SEGCAP) {
        // pad to 128 with zeros (sort places them at the tail/head)
        for (int i = t; i < SEGCAP; i += SCTA)
            if (i >= cnt) s_buf[i] = 0ULL;
        __syncthreads();

        // 2-warp register bitonic sort of 128; direction by segment parity
        const bool inv = (seg & 1u) != 0;
        const bool sorter = (t < 64);
        unsigned long long r0 = 0, r1 = 0;
        int i0 = 0, i1 = 0;
        if (sorter) {
            i0 = (int)(((t >> 5) << 6) | (t & 31u));
            i1 = i0 + 32;
            r0 = s_buf[i0]; r1 = s_buf[i1];
            #pragma unroll
            for (int k = 2; k <= 32; k <<= 1)
                #pragma unroll
                for (int j = k >> 1; j >= 1; j >>= 1) {
                    r0 = ushfl(r0, i0, j, k, inv);
                    r1 = ushfl(r1, i1, j, k, inv);
                }
            ulocal32(r0, r1, i0, 64, inv);
            #pragma unroll
            for (int j = 16; j >= 1; j >>= 1) {
                r0 = ushfl(r0, i0, j, 64, inv);
                r1 = ushfl(r1, i1, j, 64, inv);
            }
            s_buf[i0] = r0; s_buf[i1] = r1;
        }
        __syncthreads();                       // j=64 cross-warp exchange
        if (sorter) {
            const unsigned long long o0 = s_buf[i0 ^ 64];
            const unsigned long long o1 = s_buf[i1 ^ 64];
            r0 = upick(r0, o0, i0, 64, 128, inv);
            r1 = upick(r1, o1, i1, 64, 128, inv);
            ulocal32(r0, r1, i0, 128, inv);
            #pragma unroll
            for (int j = 16; j >= 1; j >>= 1) {
                r0 = ushfl(r0, i0, j, 128, inv);
                r1 = ushfl(r1, i1, j, 128, inv);
            }
            unsigned long long* dst = &g_cand[n][seg << 7];
            dst[i0] = r0; dst[i1] = r1;
        }
    }
}

// ---- generic fallback scan for unexpected sizes (unsorted slots) ----
__global__ __launch_bounds__(SCTA)
void scan_generic(const float4* __restrict__ lg, int total_f4)
{
    const unsigned S = gridDim.x * (unsigned)SCTA;
    for (unsigned i = blockIdx.x * SCTA + threadIdx.x; i < (unsigned)total_f4; i += S) {
        const float4 x = lg[i];
        if (fmaxf(fmaxf(x.x, x.y), fmaxf(x.z, x.w)) > THR) {
            const float e[4] = {x.x, x.y, x.z, x.w};
            #pragma unroll
            for (int j = 0; j < 4; j++) {
                if (e[j] > THR) {
                    const unsigned flat = i * 4u + (unsigned)j;
                    const unsigned n    = flat / (unsigned)NPB;
                    if (n < (unsigned)NB) {
                        const int p = atomicAdd(&g_cnt[n * GPAD], 1);
                        if (p < CAP)
                            g_cand[n][p] = pack(e[j], flat - n * (unsigned)NPB);
                    }
                }
            }
        }
    }
}

__global__ __launch_bounds__(BTHREADS)
void rank_kernel(const float4* __restrict__ lg,
                 const float4* __restrict__ bx,
                 const int*    __restrict__ sizes,
                 float*        __restrict__ out,
                 int presorted)
{
    __shared__ union {
        unsigned long long s[CAP];      // 8KB, sort exchange
        unsigned hist[NHIST];           // 16KB, fallback only
    } u;
    __shared__ int s_c;
    __shared__ unsigned s_tk;

    const int n   = blockIdx.x;
    const int tid = threadIdx.x;
    const int l   = tid & 31;
    const int w   = tid >> 5;
    const int i0  = w * 64 + l;         // this thread's two slots
    const int i1  = i0 + 32;

    int cnt = (n < NB) ? g_cnt[n * GPAD] : -1;
    unsigned long long r0, r1;
    bool need_full;                     // block-uniform

    if (cnt >= TOPK && cnt <= CAP) {
        if (presorted) {
            // chunks are sorted (alternating dir) incl. zero padding
            r0 = g_cand[n][i0];
            r1 = g_cand[n][i1];
            need_full = false;
        } else {
            r0 = (i0 < cnt) ? g_cand[n][i0] : 0ULL;
            r1 = (i1 < cnt) ? g_cand[n][i1] : 0ULL;
            need_full = true;
        }
    } else {
        // ---- exact fallback: histogram threshold + recollect ----
        need_full = true;
        const float4* base = lg + (size_t)n * (NPB / 4);
        for (int i = tid; i < NHIST; i += BTHREADS) u.hist[i] = 0u;
        if (tid == 0) s_c = 0;
        __syncthreads();
        for (int i = tid; i < NPB / 4; i += BTHREADS) {
            float4 v = base[i];
            atomicAdd(&u.hist[fkey(v.x) >> 20], 1u);
            atomicAdd(&u.hist[fkey(v.y) >> 20], 1u);
            atomicAdd(&u.hist[fkey(v.z) >> 20], 1u);
            atomicAdd(&u.hist[fkey(v.w) >> 20], 1u);
        }
        __syncthreads();
        if (tid == 0) {
            unsigned acc = 0; int b = NHIST - 1;
            for (; b > 0; --b) { acc += u.hist[b]; if (acc >= TOPK) break; }
            s_tk = (unsigned)b << 20;
        }
        __syncthreads();
        const unsigned tk = s_tk;
        for (int i = tid; i < CAP; i += BTHREADS) u.s[i] = 0ULL;
        __syncthreads();
        for (int i = tid; i < NPB / 4; i += BTHREADS) {
            float4 v = base[i];
            const float e[4] = {v.x, v.y, v.z, v.w};
            #pragma unroll
            for (int j = 0; j < 4; j++) {
                unsigned kk = fkey(e[j]);
                if (kk >= tk) {
                    int p = atomicAdd(&s_c, 1);
                    if (p < CAP)
                        u.s[p] = ((unsigned long long)kk << 32) |
                                 (unsigned)(0xFFFFFFFFu - (unsigned)(4 * i + j));
                }
            }
        }
        __syncthreads();
        r0 = u.s[i0];
        r1 = u.s[i1];
    }

    // reset counter for the next graph replay
    if (tid == 0 && n < NB) g_cnt[n * GPAD] = 0;

    // ---- bitonic network, descending ----
    // full path: k=2..64 (shfl/local). presorted path skips straight to k=256.
    if (need_full) {
        #pragma unroll
        for (int k = 2; k <= 32; k <<= 1)
            #pragma unroll
            for (int j = k >> 1; j >= 1; j >>= 1) {
                r0 = ushfl(r0, i0, j, k, false);
                r1 = ushfl(r1, i1, j, k, false);
            }
        ulocal32(r0, r1, i0, 64, false);
        #pragma unroll
        for (int j = 16; j >= 1; j >>= 1) {
            r0 = ushfl(r0, i0, j, 64, false);
            r1 = ushfl(r1, i1, j, 64, false);
        }
    }
    const int kstart = need_full ? 128 : 256;
    #pragma unroll
    for (int k = 128; k <= CAP; k <<= 1) {
        if (k < kstart) continue;                 // block-uniform
        u.s[i0] = r0; u.s[i1] = r1;
        __syncthreads();
        #pragma unroll
        for (int j = k >> 1; j >= 64; j >>= 1) {
            const unsigned long long o0 = u.s[i0 ^ j];
            const unsigned long long o1 = u.s[i1 ^ j];
            r0 = upick(r0, o0, i0, j, k, false);
            r1 = upick(r1, o1, i1, j, k, false);
            __syncthreads();                      // all reads done
            if (j > 64) { u.s[i0] = r0; u.s[i1] = r1; __syncthreads(); }
        }
        ulocal32(r0, r1, i0, k, false);
        #pragma unroll
        for (int j = 16; j >= 1; j >>= 1) {
            r0 = ushfl(r0, i0, j, k, false);
            r1 = ushfl(r1, i1, j, k, false);
        }
    }

    // ---- epilogue: slots < 300 decode + write straight from registers ----
    const float fx = (float)sizes[1];
    const float fy = (float)sizes[0];

    #pragma unroll
    for (int e = 0; e < 2; e++) {
        const int slot = e ? i1 : i0;
        if (slot < TOPK) {
            const unsigned long long pk = e ? r1 : r0;
            const unsigned key  = (unsigned)(pk >> 32);
            const unsigned flat = 0xFFFFFFFFu - (unsigned)(pk & 0xFFFFFFFFu);
            const float lv    = key2f(key);
            const float score = 1.0f / (1.0f + __expf(-lv));
            const unsigned q   = flat / (unsigned)NCLS;
            const unsigned lbl = flat - q * (unsigned)NCLS;
            const float4 b = bx[(size_t)n * NQ + q];       // [cx, cy, w, h]
            float2* o = reinterpret_cast<float2*>(out + ((size_t)n * TOPK + slot) * 6);
            o[0] = make_float2((float)lbl, score);
            o[1] = make_float2((b.x - 0.5f * b.z) * fx, (b.y - 0.5f * b.w) * fy);
            o[2] = make_float2(b.z * fx, b.w * fy);
        }
    }
}

extern "C" void kernel_launch(void* const* d_in, const int* in_sizes, int n_in,
                              void* d_out, int out_size)
{
    const float* logits = (const float*)d_in[0];
    const float* boxes  = (const float*)d_in[1];
    const int*   sizes  = (const int*)d_in[2];
    const int total     = in_sizes[0];
    const int N         = total / NPB;

    int presorted = 0;
    if (total == NB * NPB) {
        presorted = 1;
        scan_batched<<<NB * SEGS, SCTA>>>((const float4*)logits);
    } else {
        const int total_f4 = total / 4;
        int grid = (total_f4 + SCTA - 1) / SCTA;
        if (grid > 2048) grid = 2048;
        if (grid < 1) grid = 1;
        scan_generic<<<grid, SCTA>>>((const float4*)logits, total_f4);
    }
    rank_kernel<<<N, BTHREADS>>>((const float4*)logits, (const float4*)boxes,
                                 sizes, (float*)d_out, presorted);
}

// round 9
// speedup vs baseline: 1.0779x; 1.0779x over previous
#include <cuda_runtime.h>
#include <cuda_bf16.h>

// DETR post-processor, 2-launch pipeline:
//   scan_batched : 1 CTA per batch-segment (8 x 2500 float4 per batch), FMNMX
//                  screen at t=2.4 -> SMEM buffer via smem atomics; ONE global
//                  atomic per CTA reserves a g_cand block, coalesced flush.
//                  Measured at the LTS/DRAM ceiling (~6.3 TB/s) - do not touch.
//   rank_kernel  : per batch, register bitonic sort of 1024 packed u64 with
//                  256 threads x 4 elements (slots i, i+32, i+64, i+96):
//                  j<=16 via shfl, j=32/64 thread-local, only j>=128 via smem
//                  (6 smem phases, ~12 barriers at 8 warps vs ~25 at 16).
//                  Top-300 decoded + written straight from registers.
//                  Exact histogram fallback if count outside [300,1024].

#define NCLS    80
#define NQ      1000
#define NPB     80000
#define NF4B    20000          // float4 per batch
#define NB      256
#define TOPK    300
#define CAP     1024
#define THR     2.4f
#define SEGS    8              // CTAs per batch
#define SEGF4   2500           // float4 per CTA
#define SCTA    512
#define BUFCAP  384            // smem candidate buffer (expect 82, sigma 9)
#define GPAD    32             // g_cnt stride (128B) -> spread LTS slices
#define BTHREADS 256
#define NHIST   4096

__device__ unsigned long long g_cand[NB][CAP];
__device__ int g_cnt[NB * GPAD];

__device__ __forceinline__ unsigned fkey(float f) {
    unsigned u = __float_as_uint(f);
    return (u & 0x80000000u) ? ~u : (u | 0x80000000u);  // monotonic float->uint
}
__device__ __forceinline__ float key2f(unsigned k) {
    return (k & 0x80000000u) ? __uint_as_float(k & 0x7fffffffu)
                             : __uint_as_float(~k);
}
__device__ __forceinline__ unsigned long long pack(float val, unsigned loc) {
    return ((unsigned long long)fkey(val) << 32) | (unsigned)(0xFFFFFFFFu - loc);
}

// ---- batch-aligned scan: CTA c covers batch c/8, segment c%8 ----
__global__ __launch_bounds__(SCTA, 3)
void scan_batched(const float4* __restrict__ lg)
{
    __shared__ unsigned long long s_buf[BUFCAP];
    __shared__ int s_cnt;
    __shared__ int s_base;

    const unsigned c   = blockIdx.x;
    const unsigned n   = c >> 3;
    const unsigned seg = c & 7u;
    const unsigned t   = threadIdx.x;
    const unsigned f4base = n * (unsigned)NF4B + seg * (unsigned)SEGF4;

    if (t == 0) s_cnt = 0;
    __syncthreads();

    // 2500 = 4*512 + 452 : 4 full strides + partial 5th
    float4 v[5];
    #pragma unroll
    for (int k = 0; k < 4; k++) v[k] = lg[f4base + t + k * SCTA];
    const bool has5 = (t < (unsigned)(SEGF4 - 4 * SCTA));   // t < 452
    if (has5) v[4] = lg[f4base + t + 4 * SCTA];

    #pragma unroll
    for (int k = 0; k < 5; k++) {
        if (k == 4 && !has5) continue;
        const float4 x = v[k];
        if (fmaxf(fmaxf(x.x, x.y), fmaxf(x.z, x.w)) > THR) {  // ~3.2% taken
            const unsigned loc0 = (seg * (unsigned)SEGF4 + t + (unsigned)k * SCTA) * 4u;
            if (x.x > THR) { int p = atomicAdd(&s_cnt, 1); if (p < BUFCAP) s_buf[p] = pack(x.x, loc0 + 0u); }
            if (x.y > THR) { int p = atomicAdd(&s_cnt, 1); if (p < BUFCAP) s_buf[p] = pack(x.y, loc0 + 1u); }
            if (x.z > THR) { int p = atomicAdd(&s_cnt, 1); if (p < BUFCAP) s_buf[p] = pack(x.z, loc0 + 2u); }
            if (x.w > THR) { int p = atomicAdd(&s_cnt, 1); if (p < BUFCAP) s_buf[p] = pack(x.w, loc0 + 3u); }
        }
    }
    __syncthreads();

    const int cnt = s_cnt;
    if (t == 0) {
        if (cnt > BUFCAP) {           // buffer overflow -> poison count, force fallback
            atomicAdd(&g_cnt[n * GPAD], 1000000);
            s_base = -1;
        } else {
            s_base = atomicAdd(&g_cnt[n * GPAD], cnt);
        }
    }
    __syncthreads();

    const int base = s_base;
    if (base >= 0) {
        for (int i = t; i < cnt; i += SCTA) {
            const int p = base + i;
            if (p < CAP) g_cand[n][p] = s_buf[i];   // >CAP handled by fallback
        }
    }
}

// ---- generic fallback scan for unexpected sizes ----
__global__ __launch_bounds__(SCTA)
void scan_generic(const float4* __restrict__ lg, int total_f4)
{
    const unsigned S = gridDim.x * (unsigned)SCTA;
    for (unsigned i = blockIdx.x * SCTA + threadIdx.x; i < (unsigned)total_f4; i += S) {
        const float4 x = lg[i];
        if (fmaxf(fmaxf(x.x, x.y), fmaxf(x.z, x.w)) > THR) {
            const float e[4] = {x.x, x.y, x.z, x.w};
            #pragma unroll
            for (int j = 0; j < 4; j++) {
                if (e[j] > THR) {
                    const unsigned flat = i * 4u + (unsigned)j;
                    const unsigned n    = flat / (unsigned)NPB;
                    if (n < (unsigned)NB) {
                        const int p = atomicAdd(&g_cnt[n * GPAD], 1);
                        if (p < CAP)
                            g_cand[n][p] = pack(e[j], flat - n * (unsigned)NPB);
                    }
                }
            }
        }
    }
}

// ---- bitonic helpers (element index i, phase j, block k) ----
__device__ __forceinline__ unsigned long long upick(
    unsigned long long v, unsigned long long o, int i, int j, int k)
{
    const bool keep_max = (((i & j) == 0) == ((i & k) == 0));
    const unsigned long long mx = v > o ? v : o;
    const unsigned long long mn = v > o ? o : v;
    return keep_max ? mx : mn;
}
__device__ __forceinline__ unsigned long long ushfl(
    unsigned long long v, int i, int j, int k)
{
    const unsigned long long o = __shfl_xor_sync(0xFFFFFFFFu, v, j);
    return upick(v, o, i, j, k);
}
// local exchange of registers a (slot ia, bit j clear) and b (slot ia^j)
__device__ __forceinline__ void plocal(
    unsigned long long& a, unsigned long long& b, int ia, int k)
{
    const bool desc = ((ia & k) == 0);
    const unsigned long long hi = a > b ? a : b;
    const unsigned long long lo = a > b ? b : a;
    a = desc ? hi : lo;
    b = desc ? lo : hi;
}

__global__ __launch_bounds__(BTHREADS)
void rank_kernel(const float4* __restrict__ lg,
                 const float4* __restrict__ bx,
                 const int*    __restrict__ sizes,
                 float*        __restrict__ out)
{
    __shared__ union {
        unsigned long long s[CAP];      // 8KB, sort exchange
        unsigned hist[NHIST];           // 16KB, fallback only
    } u;
    __shared__ int s_c;
    __shared__ unsigned s_tk;

    const int n   = blockIdx.x;
    const int tid = threadIdx.x;
    const int l   = tid & 31;
    const int w   = tid >> 5;           // 8 warps, each owns 128 elements
    const int i0  = w * 128 + l;        // slots: i0, i0+32, i0+64, i0+96
    const int i1  = i0 + 32;
    const int i2  = i0 + 64;
    const int i3  = i0 + 96;

    int cnt = (n < NB) ? g_cnt[n * GPAD] : -1;
    unsigned long long r0, r1, r2, r3;

    if (cnt >= TOPK && cnt <= CAP) {
        // expected path: candidates straight into registers (coalesced)
        r0 = (i0 < cnt) ? g_cand[n][i0] : 0ULL;
        r1 = (i1 < cnt) ? g_cand[n][i1] : 0ULL;
        r2 = (i2 < cnt) ? g_cand[n][i2] : 0ULL;
        r3 = (i3 < cnt) ? g_cand[n][i3] : 0ULL;
    } else {
        // ---- exact fallback: histogram threshold + recollect ----
        const float4* base = lg + (size_t)n * (NPB / 4);
        for (int i = tid; i < NHIST; i += BTHREADS) u.hist[i] = 0u;
        if (tid == 0) s_c = 0;
        __syncthreads();
        for (int i = tid; i < NPB / 4; i += BTHREADS) {
            float4 v = base[i];
            atomicAdd(&u.hist[fkey(v.x) >> 20], 1u);
            atomicAdd(&u.hist[fkey(v.y) >> 20], 1u);
            atomicAdd(&u.hist[fkey(v.z) >> 20], 1u);
            atomicAdd(&u.hist[fkey(v.w) >> 20], 1u);
        }
        __syncthreads();
        if (tid == 0) {
            unsigned acc = 0; int b = NHIST - 1;
            for (; b > 0; --b) { acc += u.hist[b]; if (acc >= TOPK) break; }
            s_tk = (unsigned)b << 20;
        }
        __syncthreads();
        const unsigned tk = s_tk;
        for (int i = tid; i < CAP; i += BTHREADS) u.s[i] = 0ULL;
        __syncthreads();
        for (int i = tid; i < NPB / 4; i += BTHREADS) {
            float4 v = base[i];
            const float e[4] = {v.x, v.y, v.z, v.w};
            #pragma unroll
            for (int j = 0; j < 4; j++) {
                unsigned kk = fkey(e[j]);
                if (kk >= tk) {
                    int p = atomicAdd(&s_c, 1);
                    if (p < CAP)
                        u.s[p] = ((unsigned long long)kk << 32) |
                                 (unsigned)(0xFFFFFFFFu - (unsigned)(4 * i + j));
                }
            }
        }
        __syncthreads();
        r0 = u.s[i0]; r1 = u.s[i1]; r2 = u.s[i2]; r3 = u.s[i3];
        // safe: each thread reads only its own slots, and the sort's first
        // smem write to those slots is by this same thread
    }

    // reset counter for the next graph replay
    if (tid == 0 && n < NB) g_cnt[n * GPAD] = 0;

    // ---- bitonic sort, descending, 1024 elems, 4 per thread ----
    // k = 2..32 : pure shfl
    #pragma unroll
    for (int k = 2; k <= 32; k <<= 1) {
        #pragma unroll
        for (int j = k >> 1; j >= 1; j >>= 1) {
            r0 = ushfl(r0, i0, j, k); r1 = ushfl(r1, i1, j, k);
            r2 = ushfl(r2, i2, j, k); r3 = ushfl(r3, i3, j, k);
        }
    }
    // k = 64 : j=32 local, then shfl
    plocal(r0, r1, i0, 64); plocal(r2, r3, i2, 64);
    #pragma unroll
    for (int j = 16; j >= 1; j >>= 1) {
        r0 = ushfl(r0, i0, j, 64); r1 = ushfl(r1, i1, j, 64);
        r2 = ushfl(r2, i2, j, 64); r3 = ushfl(r3, i3, j, 64);
    }
    // k = 128 : j=64,32 local, then shfl  (fully within this thread's window)
    plocal(r0, r2, i0, 128); plocal(r1, r3, i1, 128);       // j=64
    plocal(r0, r1, i0, 128); plocal(r2, r3, i2, 128);       // j=32
    #pragma unroll
    for (int j = 16; j >= 1; j >>= 1) {
        r0 = ushfl(r0, i0, j, 128); r1 = ushfl(r1, i1, j, 128);
        r2 = ushfl(r2, i2, j, 128); r3 = ushfl(r3, i3, j, 128);
    }
    // k = 256..1024 : smem for j>=128, local j=64/32, shfl j<=16
    #pragma unroll
    for (int k = 256; k <= CAP; k <<= 1) {
        u.s[i0] = r0; u.s[i1] = r1; u.s[i2] = r2; u.s[i3] = r3;
        __syncthreads();
        #pragma unroll
        for (int j = k >> 1; j >= 128; j >>= 1) {
            const unsigned long long o0 = u.s[i0 ^ j];
            const unsigned long long o1 = u.s[i1 ^ j];
            const unsigned long long o2 = u.s[i2 ^ j];
            const unsigned long long o3 = u.s[i3 ^ j];
            r0 = upick(r0, o0, i0, j, k); r1 = upick(r1, o1, i1, j, k);
            r2 = upick(r2, o2, i2, j, k); r3 = upick(r3, o3, i3, j, k);
            __syncthreads();                       // all reads done
            if (j > 128) {
                u.s[i0] = r0; u.s[i1] = r1; u.s[i2] = r2; u.s[i3] = r3;
                __syncthreads();
            }
        }
        plocal(r0, r2, i0, k); plocal(r1, r3, i1, k);        // j=64
        plocal(r0, r1, i0, k); plocal(r2, r3, i2, k);        // j=32
        #pragma unroll
        for (int j = 16; j >= 1; j >>= 1) {
            r0 = ushfl(r0, i0, j, k); r1 = ushfl(r1, i1, j, k);
            r2 = ushfl(r2, i2, j, k); r3 = ushfl(r3, i3, j, k);
        }
    }

    // ---- epilogue: slots < 300 decode + write straight from registers ----
    const float fx = (float)sizes[1];
    const float fy = (float)sizes[0];

    #pragma unroll
    for (int e = 0; e < 4; e++) {
        const int slot = i0 + e * 32;
        if (slot < TOPK) {
            const unsigned long long pk = (e == 0) ? r0 : (e == 1) ? r1
                                        : (e == 2) ? r2 : r3;
            const unsigned key  = (unsigned)(pk >> 32);
            const unsigned flat = 0xFFFFFFFFu - (unsigned)(pk & 0xFFFFFFFFu);
            const float lv    = key2f(key);
            const float score = 1.0f / (1.0f + __expf(-lv));
            const unsigned q   = flat / (unsigned)NCLS;
            const unsigned lbl = flat - q * (unsigned)NCLS;
            const float4 b = bx[(size_t)n * NQ + q];       // [cx, cy, w, h]
            float2* o = reinterpret_cast<float2*>(out + ((size_t)n * TOPK + slot) * 6);
            o[0] = make_float2((float)lbl, score);
            o[1] = make_float2((b.x - 0.5f * b.z) * fx, (b.y - 0.5f * b.w) * fy);
            o[2] = make_float2(b.z * fx, b.w * fy);
        }
    }
}

extern "C" void kernel_launch(void* const* d_in, const int* in_sizes, int n_in,
                              void* d_out, int out_size)
{
    const float* logits = (const float*)d_in[0];
    const float* boxes  = (const float*)d_in[1];
    const int*   sizes  = (const int*)d_in[2];
    const int total     = in_sizes[0];
    const int N         = total / NPB;

    if (total == NB * NPB) {
        scan_batched<<<NB * SEGS, SCTA>>>((const float4*)logits);
    } else {
        const int total_f4 = total / 4;
        int grid = (total_f4 + SCTA - 1) / SCTA;
        if (grid > 2048) grid = 2048;
        if (grid < 1) grid = 1;
        scan_generic<<<grid, SCTA>>>((const float4*)logits, total_f4);
    }
    rank_kernel<<<N, BTHREADS>>>((const float4*)logits, (const float4*)boxes,
                                 sizes, (float*)d_out);
}